// round 17
// baseline (speedup 1.0000x reference)
#include <cuda_runtime.h>
#include <math_constants.h>

// Cumulative max along H for x[B=32, C=1, H=1024, W=2048] fp32.
// Single streaming pass: 256 MB read + 256 MB write (the traffic floor).
//
// R16 = R5 (3x-reproduced optimum: float2 columns, 32768 threads,
// 1024x32 grid, rolling ring-buffer U=32, ld.cs loads) with ONE change:
// stores use st.cg instead of st.cs. This isolates the two variables
// R14 conflated:
//   - L1 path: st.cg bypasses L1 like st.cs (R14's default stores
//     write-allocated through L1: L1 38.9->59.5%, regressed).
//   - L2 eviction: st.cg uses NORMAL priority (vs evict-first), letting
//     dirty lines pool in the 126 MB L2 and drain via the writeback
//     scheduler in coarser same-direction bursts -> fewer DRAM bus
//     turnarounds on the interleaved 50/50 R/W stream, which the model
//     says is the remaining ~21% gap to spec.
//
// Sweep record (kernel DRAM%):
//   width:  float4 66.9 < float2 78.6 > float1 76.5
//   depth:  chunk-16 68.4 < roll-32 78.6/78.8/77.6 > roll-44 73.7
//   stores: default 72.2 < st.cs 78.6 ; st.cg = this experiment
//   pairing: neutral. Traffic: single pass is the floor.

static constexpr int B = 32;
static constexpr int H = 1024;
static constexpr int W = 2048;
static constexpr int W2 = W / 2;            // 1024 float2 per row
static constexpr int NCOLS = B * W2;        // 32768 threads
static constexpr int U = 32;                // pipeline depth (float2 loads)
static constexpr int NCHUNK = H / U;        // 32 chunks

__global__ void __launch_bounds__(32)
cummax_h_kernel(const float2* __restrict__ x, float2* __restrict__ out) {
    int c = blockIdx.x * blockDim.x + threadIdx.x;   // 0 .. NCOLS-1

    int b  = c >> 10;          // c / 1024
    int w2 = c & (W2 - 1);     // c % 1024

    const float2* __restrict__ p = x   + (size_t)b * H * W2 + w2;
    float2*       __restrict__ q = out + (size_t)b * H * W2 + w2;

    float2 m = make_float2(-CUDART_INF_F, -CUDART_INF_F);

    float2 buf[U];

    // Prologue: fill the pipeline with rows 0..U-1.
    #pragma unroll
    for (int i = 0; i < U; i++)
        buf[i] = __ldcs(p + (size_t)i * W2);

    // Steady state: consume row hCur+i while refilling with row hCur+i+U.
    // The refill load is independent of the fmax chain and issues first,
    // so U loads stay in flight continuously with no drain windows.
    for (int cc = 0; cc < NCHUNK - 1; cc++) {
        int hCur = cc * U;
        int hNxt = hCur + U;
        #pragma unroll
        for (int i = 0; i < U; i++) {
            float2 v = buf[i];
            buf[i] = __ldcs(p + (size_t)(hNxt + i) * W2);
            m.x = fmaxf(m.x, v.x);
            m.y = fmaxf(m.y, v.y);
            __stcg(q + (size_t)(hCur + i) * W2, m);   // L1-bypass, normal L2
        }
    }

    // Epilogue: drain the last chunk (rows H-U .. H-1).
    {
        int hCur = (NCHUNK - 1) * U;
        #pragma unroll
        for (int i = 0; i < U; i++) {
            m.x = fmaxf(m.x, buf[i].x);
            m.y = fmaxf(m.y, buf[i].y);
            __stcg(q + (size_t)(hCur + i) * W2, m);
        }
    }
}

extern "C" void kernel_launch(void* const* d_in, const int* in_sizes, int n_in,
                              void* d_out, int out_size) {
    const float2* x   = (const float2*)d_in[0];
    float2*       out = (float2*)d_out;

    // 1024 blocks x 32 threads = 32768 threads, one per float2 column.
    cummax_h_kernel<<<NCOLS / 32, 32>>>(x, out);
}